// round 6
// baseline (speedup 1.0000x reference)
#include <cuda_runtime.h>

#define NN 100000
#define EE 1250000
#define DD 64
#define LL 5
#define GG 128
#define TT 37
#define DE 7
#define NCH 196          // ceil(NN/512)

#define SC_BLOCKS 1024
#define SC_HW (SC_BLOCKS * 16)            // half-warps in scatter grid
#define EPH ((EE + SC_HW - 1) / SC_HW)    // edges per half-warp chunk

typedef unsigned long long ull;

__device__ __forceinline__ ull pack2(float lo, float hi) {
    ull r;
    asm("mov.b64 %0, {%1,%2};" : "=l"(r)
        : "r"(__float_as_uint(lo)), "r"(__float_as_uint(hi)));
    return r;
}
__device__ __forceinline__ void unpack2(ull v, float& lo, float& hi) {
    unsigned a, b;
    asm("mov.b64 {%0,%1}, %2;" : "=r"(a), "=r"(b) : "l"(v));
    lo = __uint_as_float(a);
    hi = __uint_as_float(b);
}
#define FMA2(d, a, b, c) \
    asm("fma.rn.f32x2 %0, %1, %2, %3;" : "=l"(d) : "l"(a), "l"(b), "l"(c))
#define ADD2(d, a, b) \
    asm("add.rn.f32x2 %0, %1, %2;" : "=l"(d) : "l"(a), "l"(b))

// ---------------- device scratch ----------------
__device__ float d_hbuf[LL * NN * DD];    // per-layer node embeddings
__device__ float d_agg[NN * DD];
__device__ int2  d_edge[EE];              // raw {src,dst}
__device__ int2  d_edgeP[EE];             // {src,dst} sorted by src
__device__ float d_eattrD[EE * 16];       // attrs, src order, dup'd pairs (a,a)
__device__ int   d_deg[NN];               // out-degree
__device__ int   d_off[NN];
__device__ int   d_cur[NN];
__device__ int   d_chtot[256];
__device__ int   d_choff[256];
__device__ int   d_batch32[NN];
__device__ float d_gpool[GG * LL * DD];
__device__ int   d_flags[2];

// ---------------- dtype detection ----------------
__global__ void detect_kernel(const unsigned* __restrict__ ei,
                              const unsigned* __restrict__ batch) {
    if (threadIdx.x == 0 && blockIdx.x == 0) {
        int f = 1;
        for (int k = 0; k < 64; k++)
            if (ei[1000001 + 2 * k] != 0u) { f = 0; break; }
        d_flags[0] = f;
        int fb = 1;
        for (int k = 0; k < 64; k++)
            if (batch[(NN - 1) - 2 * k] != 0u) { fb = 0; break; }
        d_flags[1] = fb;
    }
}

// ---------------- zero deg + gpool ----------------
__global__ void zero_kernel() {
    int i = blockIdx.x * blockDim.x + threadIdx.x;
    if (i < NN) d_deg[i] = 0;
    if (i < GG * LL * DD) d_gpool[i] = 0.0f;
}

// ---------------- convert indices (+ out-degree histogram) ----------------
__global__ void convert_kernel(const void* __restrict__ ei,
                               const void* __restrict__ batch) {
    int i = blockIdx.x * blockDim.x + threadIdx.x;
    int e64 = d_flags[0];
    int b64 = d_flags[1];
    if (i < EE) {
        int s, d;
        if (e64) {
            const long long* p = (const long long*)ei;
            s = (int)p[i]; d = (int)p[i + EE];
        } else {
            const int* p = (const int*)ei;
            s = p[i]; d = p[i + EE];
        }
        d_edge[i] = make_int2(s, d);
        atomicAdd(&d_deg[s], 1);
    }
    if (i < NN) {
        if (b64) {
            const long long* p = (const long long*)batch;
            d_batch32[i] = (int)p[i];
        } else {
            const int* p = (const int*)batch;
            d_batch32[i] = p[i];
        }
    }
}

// ---------------- scans ----------------
__global__ void scan1_kernel() {
    __shared__ int sm[512];
    int t = threadIdx.x;
    int g = blockIdx.x * 512 + t;
    int v = (g < NN) ? d_deg[g] : 0;
    sm[t] = v;
    __syncthreads();
    for (int off = 1; off < 512; off <<= 1) {
        int x = (t >= off) ? sm[t - off] : 0;
        __syncthreads();
        sm[t] += x;
        __syncthreads();
    }
    if (g < NN) d_off[g] = sm[t] - v;
    if (t == 511) d_chtot[blockIdx.x] = sm[511];
}

__global__ void scan2_kernel() {
    __shared__ int sm[256];
    int t = threadIdx.x;
    int v = (t < NCH) ? d_chtot[t] : 0;
    sm[t] = v;
    __syncthreads();
    for (int off = 1; off < 256; off <<= 1) {
        int x = (t >= off) ? sm[t - off] : 0;
        __syncthreads();
        sm[t] += x;
        __syncthreads();
    }
    if (t < NCH) d_choff[t] = sm[t] - v;
}

__global__ void scan3_kernel() {
    int t = threadIdx.x;
    int g = blockIdx.x * 512 + t;
    if (g < NN) {
        int o = d_off[g] + d_choff[blockIdx.x];
        d_off[g] = o;
        d_cur[g] = o;
    }
}

// ---------------- permute edges into src-sorted order ---------------------
// Attr stored as duplicated pairs: (a0,a0),(a1,a1),...,(a6,a6),(0,0)
__global__ void csrscat_kernel(const float* __restrict__ eattr) {
    int e = blockIdx.x * blockDim.x + threadIdx.x;
    if (e >= EE) return;
    int2 sd = d_edge[e];
    int pos = atomicAdd(&d_cur[sd.x], 1);
    d_edgeP[pos] = sd;
    const float* ea = eattr + (size_t)e * DE;
    float a0 = ea[0], a1 = ea[1], a2 = ea[2], a3 = ea[3],
          a4 = ea[4], a5 = ea[5], a6 = ea[6];
    float4* p = (float4*)(d_eattrD + (size_t)pos * 16);
    p[0] = make_float4(a0, a0, a1, a1);
    p[1] = make_float4(a2, a2, a3, a3);
    p[2] = make_float4(a4, a4, a5, a5);
    p[3] = make_float4(a6, a6, 0.0f, 0.0f);
}

// ---------------- agg = (1 + eps[0]) * x  (layer 0 only) ------------------
__global__ void pre_kernel(const float* __restrict__ hprev,
                           const float* __restrict__ eps) {
    int i = blockIdx.x * blockDim.x + threadIdx.x;
    const int n4 = NN * DD / 4;
    if (i >= n4) return;
    float s = 1.0f + __ldg(eps);
    float4 v = ((const float4*)hprev)[i];
    v.x *= s; v.y *= s; v.z *= s; v.w *= s;
    ((float4*)d_agg)[i] = v;
}

// ---------------- scatter: agg[dst] += relu(h[src] + edge_emb) ------------
// Edges sorted by src (L1-resident h rows). f32x2 packed math throughout.
__global__ void __launch_bounds__(256) scatter_kernel(
        const float* __restrict__ hprev,
        const float* __restrict__ We,
        const float* __restrict__ be) {
    int lane = threadIdx.x & 31;
    int c = (lane & 15) * 4;

    ull wk01[7], wk23[7];
#pragma unroll
    for (int k = 0; k < 7; k++) {
        longlong2 wq = *(const longlong2*)(We + k * DD + c);
        wk01[k] = (ull)wq.x;
        wk23[k] = (ull)wq.y;
    }
    longlong2 bq = *(const longlong2*)(be + c);
    ull b01 = (ull)bq.x, b23 = (ull)bq.y;

    int hwid = (blockIdx.x * blockDim.x + threadIdx.x) >> 4;
    long long e0 = (long long)hwid * EPH;
    long long e1 = e0 + EPH;
    if (e1 > EE) e1 = EE;

#pragma unroll 2
    for (long long e = e0; e < e1; e++) {
        int2 sd = __ldg(&d_edgeP[e]);
        const longlong2* ad = (const longlong2*)(d_eattrD + (size_t)e * 16);
        longlong2 q0 = __ldg(ad + 0);     // (a0,a0),(a1,a1)
        longlong2 q1 = __ldg(ad + 1);     // (a2,a2),(a3,a3)
        longlong2 q2 = __ldg(ad + 2);     // (a4,a4),(a5,a5)
        longlong2 q3 = __ldg(ad + 3);     // (a6,a6),(0,0)
        longlong2 hq = __ldg((const longlong2*)(hprev + (size_t)sd.x * DD + c));

        ull m01 = b01, m23 = b23;
        FMA2(m01, (ull)q0.x, wk01[0], m01); FMA2(m23, (ull)q0.x, wk23[0], m23);
        FMA2(m01, (ull)q0.y, wk01[1], m01); FMA2(m23, (ull)q0.y, wk23[1], m23);
        FMA2(m01, (ull)q1.x, wk01[2], m01); FMA2(m23, (ull)q1.x, wk23[2], m23);
        FMA2(m01, (ull)q1.y, wk01[3], m01); FMA2(m23, (ull)q1.y, wk23[3], m23);
        FMA2(m01, (ull)q2.x, wk01[4], m01); FMA2(m23, (ull)q2.x, wk23[4], m23);
        FMA2(m01, (ull)q2.y, wk01[5], m01); FMA2(m23, (ull)q2.y, wk23[5], m23);
        FMA2(m01, (ull)q3.x, wk01[6], m01); FMA2(m23, (ull)q3.x, wk23[6], m23);

        ADD2(m01, m01, (ull)hq.x);
        ADD2(m23, m23, (ull)hq.y);

        float f0, f1, f2, f3;
        unpack2(m01, f0, f1);
        unpack2(m23, f2, f3);
        f0 = fmaxf(f0, 0.0f);
        f1 = fmaxf(f1, 0.0f);
        f2 = fmaxf(f2, 0.0f);
        f3 = fmaxf(f3, 0.0f);

        float* ap = d_agg + (size_t)sd.y * DD + c;
        asm volatile("red.global.add.v4.f32 [%0], {%1,%2,%3,%4};"
                     :: "l"(ap), "f"(f0), "f"(f1), "f"(f2), "f"(f3)
                     : "memory");
    }
}

// ---------------- MLP + fused pool --------------------------------------
// h_out = relu(agg @ W + b); agg_next = s*h_out; gpool[batch] += h_out
// f32x2 packed accumulators (cols packed), transposed u tile (stride 72).
#define UTS 72
__global__ void __launch_bounds__(256) mlp_kernel(
        const float* __restrict__ W,
        const float* __restrict__ b,
        float* __restrict__ hout,
        const float* __restrict__ eps, int l) {
    __shared__ float Ws[DD * DD];     // 16 KB
    __shared__ float uT[DD * UTS];    // 18 KB, uT[k*72 + node]

    int t = threadIdx.x;
    for (int i = t; i < DD * DD / 4; i += 256)
        ((float4*)Ws)[i] = ((const float4*)W)[i];

    int node0 = blockIdx.x * 64;
    for (int i = t; i < 64 * 16; i += 256) {
        int nl = i >> 4;                 // local node 0..63
        int kp = i & 15;                 // float4 index along k
        int node = node0 + nl;
        float4 v = (node < NN)
            ? ((const float4*)(d_agg + (size_t)node * DD))[kp]
            : make_float4(0.f, 0.f, 0.f, 0.f);
        uT[(kp * 4 + 0) * UTS + nl] = v.x;
        uT[(kp * 4 + 1) * UTS + nl] = v.y;
        uT[(kp * 4 + 2) * UTS + nl] = v.z;
        uT[(kp * 4 + 3) * UTS + nl] = v.w;
    }
    __syncthreads();

    float snext = (l < LL - 1) ? (1.0f + __ldg(eps + l + 1)) : 0.0f;

    int c4 = (t & 15) * 4;
    int n4 = (t >> 4) * 4;

    longlong2 bq = *(const longlong2*)(b + c4);
    ull acc01[4], acc23[4];
#pragma unroll
    for (int ni = 0; ni < 4; ni++) {
        acc01[ni] = (ull)bq.x;
        acc23[ni] = (ull)bq.y;
    }

#pragma unroll 8
    for (int k = 0; k < DD; k++) {
        float4 uv = *(const float4*)(uT + k * UTS + n4);
        longlong2 wq = *(const longlong2*)(Ws + k * DD + c4);
        ull w01 = (ull)wq.x, w23 = (ull)wq.y;
        ull u0 = pack2(uv.x, uv.x);
        ull u1 = pack2(uv.y, uv.y);
        ull u2 = pack2(uv.z, uv.z);
        ull u3 = pack2(uv.w, uv.w);
        FMA2(acc01[0], u0, w01, acc01[0]); FMA2(acc23[0], u0, w23, acc23[0]);
        FMA2(acc01[1], u1, w01, acc01[1]); FMA2(acc23[1], u1, w23, acc23[1]);
        FMA2(acc01[2], u2, w01, acc01[2]); FMA2(acc23[2], u2, w23, acc23[2]);
        FMA2(acc01[3], u3, w01, acc01[3]); FMA2(acc23[3], u3, w23, acc23[3]);
    }

#pragma unroll
    for (int ni = 0; ni < 4; ni++) {
        int node = node0 + n4 + ni;
        if (node < NN) {
            float o0, o1, o2, o3;
            unpack2(acc01[ni], o0, o1);
            unpack2(acc23[ni], o2, o3);
            o0 = fmaxf(o0, 0.0f);
            o1 = fmaxf(o1, 0.0f);
            o2 = fmaxf(o2, 0.0f);
            o3 = fmaxf(o3, 0.0f);
            float4 o = make_float4(o0, o1, o2, o3);
            *(float4*)(hout + (size_t)node * DD + c4) = o;
            if (l < LL - 1) {
                float4 a;
                a.x = snext * o0; a.y = snext * o1;
                a.z = snext * o2; a.w = snext * o3;
                *(float4*)(d_agg + (size_t)node * DD + c4) = a;
            }
            int g = d_batch32[node];
            float* gp = d_gpool + (size_t)g * (LL * DD) + l * DD + c4;
            asm volatile("red.global.add.v4.f32 [%0], {%1,%2,%3,%4};"
                         :: "l"(gp), "f"(o0), "f"(o1), "f"(o2), "f"(o3)
                         : "memory");
        }
    }
}

// ---------------- predictor ----------------------------------------------
__device__ __forceinline__ int lower_bound_i(const int* a, int n, int v) {
    int lo = 0, hi = n;
    while (lo < hi) {
        int m = (lo + hi) >> 1;
        if (a[m] < v) lo = m + 1; else hi = m;
    }
    return lo;
}

__global__ void pred_kernel(const float* __restrict__ Wp,
                            const float* __restrict__ bp,
                            float* __restrict__ out) {
    int i = blockIdx.x * blockDim.x + threadIdx.x;
    if (i >= GG * TT) return;
    int g = i / TT, t = i % TT;
    int start = lower_bound_i(d_batch32, NN, g);
    int end   = lower_bound_i(d_batch32, NN, g + 1);
    int cnt = end - start;
    float inv = 1.0f / (float)(cnt > 0 ? cnt : 1);
    const float* gp = d_gpool + g * (LL * DD);
    float s = 0.0f;
    for (int c = 0; c < LL * DD; c++)
        s = fmaf(gp[c], __ldg(Wp + c * TT + t), s);
    out[i] = fmaf(inv, s, __ldg(bp + t));
}

// ---------------- launch -------------------------------------------------
extern "C" void kernel_launch(void* const* d_in, const int* in_sizes, int n_in,
                              void* d_out, int out_size) {
    const float* x     = (const float*)d_in[0];
    const void*  ei    = d_in[1];
    const float* eattr = (const float*)d_in[2];
    const void*  batch = d_in[3];
    const float* We    = (const float*)d_in[4];
    const float* be    = (const float*)d_in[5];
    const float* eps   = (const float*)d_in[6];
    const float* Wm    = (const float*)d_in[7];
    const float* bm    = (const float*)d_in[8];
    const float* Wp    = (const float*)d_in[9];
    const float* bp    = (const float*)d_in[10];
    float* out = (float*)d_out;

    detect_kernel<<<1, 32>>>((const unsigned*)ei, (const unsigned*)batch);
    zero_kernel<<<(NN + 255) / 256, 256>>>();
    convert_kernel<<<(EE + 255) / 256, 256>>>(ei, batch);
    scan1_kernel<<<NCH, 512>>>();
    scan2_kernel<<<1, 256>>>();
    scan3_kernel<<<NCH, 512>>>();
    csrscat_kernel<<<(EE + 255) / 256, 256>>>(eattr);

    float* hbuf = nullptr;
    cudaGetSymbolAddress((void**)&hbuf, d_hbuf);

    pre_kernel<<<(NN * DD / 4 + 255) / 256, 256>>>(x, eps);

    const float* hprev = x;
    for (int l = 0; l < LL; l++) {
        scatter_kernel<<<SC_BLOCKS, 256>>>(hprev, We, be);
        float* hout = hbuf + (size_t)l * NN * DD;
        mlp_kernel<<<(NN + 63) / 64, 256>>>(Wm + l * DD * DD, bm + l * DD,
                                            hout, eps, l);
        hprev = hout;
    }

    pred_kernel<<<(GG * TT + 255) / 256, 256>>>(Wp, bp, out);
}

// round 8
// speedup vs baseline: 1.2463x; 1.2463x over previous
#include <cuda_runtime.h>

#define NN 100000
#define EE 1250000
#define DD 64
#define LL 5
#define GG 128
#define TT 37
#define DE 7
#define NCH 196          // ceil(NN/512)

#define SC_BLOCKS 1024
#define SC_HW (SC_BLOCKS * 16)            // half-warps in scatter grid
#define EPH ((EE + SC_HW - 1) / SC_HW)    // edges per half-warp chunk

// ---------------- device scratch ----------------
__device__ float d_hbuf[LL * NN * DD];    // per-layer node embeddings
__device__ float d_agg[NN * DD];
__device__ int2  d_edge[EE];              // raw {src,dst}
__device__ int2  d_edgeP[EE];             // {src,dst} sorted by src
__device__ float d_eattrP[EE * 8];        // edge attrs permuted to src order
__device__ int   d_deg[NN];               // out-degree
__device__ int   d_off[NN];
__device__ int   d_cur[NN];
__device__ int   d_chtot[256];
__device__ int   d_choff[256];
__device__ int   d_batch32[NN];
__device__ float d_gpool[GG * LL * DD];
__device__ int   d_flags[2];

// ---------------- dtype detection ----------------
__global__ void detect_kernel(const unsigned* __restrict__ ei,
                              const unsigned* __restrict__ batch) {
    if (threadIdx.x == 0 && blockIdx.x == 0) {
        int f = 1;
        for (int k = 0; k < 64; k++)
            if (ei[1000001 + 2 * k] != 0u) { f = 0; break; }
        d_flags[0] = f;
        int fb = 1;
        for (int k = 0; k < 64; k++)
            if (batch[(NN - 1) - 2 * k] != 0u) { fb = 0; break; }
        d_flags[1] = fb;
    }
}

// ---------------- zero deg + gpool ----------------
__global__ void zero_kernel() {
    int i = blockIdx.x * blockDim.x + threadIdx.x;
    if (i < NN) d_deg[i] = 0;
    if (i < GG * LL * DD) d_gpool[i] = 0.0f;
}

// ---------------- convert indices (+ out-degree histogram) ----------------
__global__ void convert_kernel(const void* __restrict__ ei,
                               const void* __restrict__ batch) {
    int i = blockIdx.x * blockDim.x + threadIdx.x;
    int e64 = d_flags[0];
    int b64 = d_flags[1];
    if (i < EE) {
        int s, d;
        if (e64) {
            const long long* p = (const long long*)ei;
            s = (int)p[i]; d = (int)p[i + EE];
        } else {
            const int* p = (const int*)ei;
            s = p[i]; d = p[i + EE];
        }
        d_edge[i] = make_int2(s, d);
        atomicAdd(&d_deg[s], 1);
    }
    if (i < NN) {
        if (b64) {
            const long long* p = (const long long*)batch;
            d_batch32[i] = (int)p[i];
        } else {
            const int* p = (const int*)batch;
            d_batch32[i] = p[i];
        }
    }
}

// ---------------- scans ----------------
__global__ void scan1_kernel() {
    __shared__ int sm[512];
    int t = threadIdx.x;
    int g = blockIdx.x * 512 + t;
    int v = (g < NN) ? d_deg[g] : 0;
    sm[t] = v;
    __syncthreads();
    for (int off = 1; off < 512; off <<= 1) {
        int x = (t >= off) ? sm[t - off] : 0;
        __syncthreads();
        sm[t] += x;
        __syncthreads();
    }
    if (g < NN) d_off[g] = sm[t] - v;
    if (t == 511) d_chtot[blockIdx.x] = sm[511];
}

__global__ void scan2_kernel() {
    __shared__ int sm[256];
    int t = threadIdx.x;
    int v = (t < NCH) ? d_chtot[t] : 0;
    sm[t] = v;
    __syncthreads();
    for (int off = 1; off < 256; off <<= 1) {
        int x = (t >= off) ? sm[t - off] : 0;
        __syncthreads();
        sm[t] += x;
        __syncthreads();
    }
    if (t < NCH) d_choff[t] = sm[t] - v;
}

__global__ void scan3_kernel() {
    int t = threadIdx.x;
    int g = blockIdx.x * 512 + t;
    if (g < NN) {
        int o = d_off[g] + d_choff[blockIdx.x];
        d_off[g] = o;
        d_cur[g] = o;
    }
}

// ---------------- permute edges into src-sorted order ---------------------
__global__ void csrscat_kernel(const float* __restrict__ eattr) {
    int e = blockIdx.x * blockDim.x + threadIdx.x;
    if (e >= EE) return;
    int2 sd = d_edge[e];
    int pos = atomicAdd(&d_cur[sd.x], 1);
    d_edgeP[pos] = sd;
    const float* ea = eattr + (size_t)e * DE;
    float4 v0 = make_float4(ea[0], ea[1], ea[2], ea[3]);
    float4 v1 = make_float4(ea[4], ea[5], ea[6], 0.0f);
    float4* p = (float4*)(d_eattrP + (size_t)pos * 8);
    p[0] = v0; p[1] = v1;
}

// ---------------- agg = (1 + eps[0]) * x  (layer 0 only) ------------------
__global__ void pre_kernel(const float* __restrict__ hprev,
                           const float* __restrict__ eps) {
    int i = blockIdx.x * blockDim.x + threadIdx.x;
    const int n4 = NN * DD / 4;
    if (i >= n4) return;
    float s = 1.0f + __ldg(eps);
    float4 v = ((const float4*)hprev)[i];
    v.x *= s; v.y *= s; v.z *= s; v.w *= s;
    ((float4*)d_agg)[i] = v;
}

// ---------------- scatter: agg[dst] += relu(h[src] + edge_emb) ------------
// Edges sorted by src; each half-warp owns a CONTIGUOUS chunk so h[src]
// loads hit L1 (~92% of edges reuse the previous row). RED is fire-and-forget.
__global__ void __launch_bounds__(256) scatter_kernel(
        const float* __restrict__ hprev,
        const float* __restrict__ We,
        const float* __restrict__ be) {
    int lane = threadIdx.x & 31;
    int c = (lane & 15) * 4;

    float4 w0 = *(const float4*)(We + 0 * DD + c);
    float4 w1 = *(const float4*)(We + 1 * DD + c);
    float4 w2 = *(const float4*)(We + 2 * DD + c);
    float4 w3 = *(const float4*)(We + 3 * DD + c);
    float4 w4 = *(const float4*)(We + 4 * DD + c);
    float4 w5 = *(const float4*)(We + 5 * DD + c);
    float4 w6 = *(const float4*)(We + 6 * DD + c);
    float4 bv = *(const float4*)(be + c);

    int hwid = (blockIdx.x * blockDim.x + threadIdx.x) >> 4;
    long long e0 = (long long)hwid * EPH;
    long long e1 = e0 + EPH;
    if (e1 > EE) e1 = EE;

#pragma unroll 2
    for (long long e = e0; e < e1; e++) {
        int2 sd = __ldg(&d_edgeP[e]);
        float4 a0 = __ldg((const float4*)(d_eattrP + (size_t)e * 8));
        float4 a1 = __ldg((const float4*)(d_eattrP + (size_t)e * 8 + 4));
        float4 hv = __ldg((const float4*)(hprev + (size_t)sd.x * DD + c));

        float m0 = bv.x, m1 = bv.y, m2 = bv.z, m3 = bv.w;
        m0 = fmaf(a0.x, w0.x, m0); m1 = fmaf(a0.x, w0.y, m1);
        m2 = fmaf(a0.x, w0.z, m2); m3 = fmaf(a0.x, w0.w, m3);
        m0 = fmaf(a0.y, w1.x, m0); m1 = fmaf(a0.y, w1.y, m1);
        m2 = fmaf(a0.y, w1.z, m2); m3 = fmaf(a0.y, w1.w, m3);
        m0 = fmaf(a0.z, w2.x, m0); m1 = fmaf(a0.z, w2.y, m1);
        m2 = fmaf(a0.z, w2.z, m2); m3 = fmaf(a0.z, w2.w, m3);
        m0 = fmaf(a0.w, w3.x, m0); m1 = fmaf(a0.w, w3.y, m1);
        m2 = fmaf(a0.w, w3.z, m2); m3 = fmaf(a0.w, w3.w, m3);
        m0 = fmaf(a1.x, w4.x, m0); m1 = fmaf(a1.x, w4.y, m1);
        m2 = fmaf(a1.x, w4.z, m2); m3 = fmaf(a1.x, w4.w, m3);
        m0 = fmaf(a1.y, w5.x, m0); m1 = fmaf(a1.y, w5.y, m1);
        m2 = fmaf(a1.y, w5.z, m2); m3 = fmaf(a1.y, w5.w, m3);
        m0 = fmaf(a1.z, w6.x, m0); m1 = fmaf(a1.z, w6.y, m1);
        m2 = fmaf(a1.z, w6.z, m2); m3 = fmaf(a1.z, w6.w, m3);

        m0 = fmaxf(m0 + hv.x, 0.0f);
        m1 = fmaxf(m1 + hv.y, 0.0f);
        m2 = fmaxf(m2 + hv.z, 0.0f);
        m3 = fmaxf(m3 + hv.w, 0.0f);

        float* ap = d_agg + (size_t)sd.y * DD + c;
        asm volatile("red.global.add.v4.f32 [%0], {%1,%2,%3,%4};"
                     :: "l"(ap), "f"(m0), "f"(m1), "f"(m2), "f"(m3)
                     : "memory");
    }
}

// ---------------- MLP + fused pool ---------------------------------------
// h_out = relu(agg @ W + b); agg_next = s*h_out; gpool[batch] += h_out
__global__ void __launch_bounds__(256) mlp_kernel(
        const float* __restrict__ W,
        const float* __restrict__ b,
        float* __restrict__ hout,
        const float* __restrict__ eps, int l) {
    __shared__ float Ws[DD * DD];
    __shared__ float bs[DD];
    __shared__ float u[64 * DD];

    int t = threadIdx.x;
    for (int i = t; i < DD * DD / 4; i += 256)
        ((float4*)Ws)[i] = ((const float4*)W)[i];
    if (t < DD) bs[t] = b[t];

    int node0 = blockIdx.x * 64;
    for (int i = t; i < 64 * 16; i += 256) {
        int node = node0 + (i >> 4);
        float4 v = (node < NN)
            ? ((const float4*)(d_agg + (size_t)node * DD))[i & 15]
            : make_float4(0.f, 0.f, 0.f, 0.f);
        ((float4*)u)[i] = v;
    }
    __syncthreads();

    float snext = (l < LL - 1) ? (1.0f + __ldg(eps + l + 1)) : 0.0f;

    int c4 = (t & 15) * 4;
    int n4 = (t >> 4) * 4;

    float acc[4][4];
#pragma unroll
    for (int ni = 0; ni < 4; ni++) {
        acc[ni][0] = bs[c4 + 0];
        acc[ni][1] = bs[c4 + 1];
        acc[ni][2] = bs[c4 + 2];
        acc[ni][3] = bs[c4 + 3];
    }

#pragma unroll 8
    for (int k = 0; k < DD; k++) {
        float4 w = *(const float4*)(Ws + k * DD + c4);
#pragma unroll
        for (int ni = 0; ni < 4; ni++) {
            float uv = u[(n4 + ni) * DD + k];
            acc[ni][0] = fmaf(uv, w.x, acc[ni][0]);
            acc[ni][1] = fmaf(uv, w.y, acc[ni][1]);
            acc[ni][2] = fmaf(uv, w.z, acc[ni][2]);
            acc[ni][3] = fmaf(uv, w.w, acc[ni][3]);
        }
    }

#pragma unroll
    for (int ni = 0; ni < 4; ni++) {
        int node = node0 + n4 + ni;
        if (node < NN) {
            float o0 = fmaxf(acc[ni][0], 0.0f);
            float o1 = fmaxf(acc[ni][1], 0.0f);
            float o2 = fmaxf(acc[ni][2], 0.0f);
            float o3 = fmaxf(acc[ni][3], 0.0f);
            *(float4*)(hout + (size_t)node * DD + c4) =
                make_float4(o0, o1, o2, o3);
            if (l < LL - 1) {
                *(float4*)(d_agg + (size_t)node * DD + c4) =
                    make_float4(snext * o0, snext * o1, snext * o2, snext * o3);
            }
            int g = d_batch32[node];
            float* gp = d_gpool + (size_t)g * (LL * DD) + l * DD + c4;
            asm volatile("red.global.add.v4.f32 [%0], {%1,%2,%3,%4};"
                         :: "l"(gp), "f"(o0), "f"(o1), "f"(o2), "f"(o3)
                         : "memory");
        }
    }
}

// ---------------- predictor (divides pooled sum by count) ------------------
__device__ __forceinline__ int lower_bound_i(const int* a, int n, int v) {
    int lo = 0, hi = n;
    while (lo < hi) {
        int m = (lo + hi) >> 1;
        if (a[m] < v) lo = m + 1; else hi = m;
    }
    return lo;
}

__global__ void pred_kernel(const float* __restrict__ Wp,
                            const float* __restrict__ bp,
                            float* __restrict__ out) {
    int i = blockIdx.x * blockDim.x + threadIdx.x;
    if (i >= GG * TT) return;
    int g = i / TT, t = i % TT;
    int start = lower_bound_i(d_batch32, NN, g);
    int end   = lower_bound_i(d_batch32, NN, g + 1);
    int cnt = end - start;
    float inv = 1.0f / (float)(cnt > 0 ? cnt : 1);
    const float* gp = d_gpool + g * (LL * DD);
    float s = 0.0f;
    for (int c = 0; c < LL * DD; c++)
        s = fmaf(gp[c], __ldg(Wp + c * TT + t), s);
    out[i] = fmaf(inv, s, __ldg(bp + t));
}

// ---------------- launch -------------------------------------------------
extern "C" void kernel_launch(void* const* d_in, const int* in_sizes, int n_in,
                              void* d_out, int out_size) {
    const float* x     = (const float*)d_in[0];
    const void*  ei    = d_in[1];
    const float* eattr = (const float*)d_in[2];
    const void*  batch = d_in[3];
    const float* We    = (const float*)d_in[4];
    const float* be    = (const float*)d_in[5];
    const float* eps   = (const float*)d_in[6];
    const float* Wm    = (const float*)d_in[7];
    const float* bm    = (const float*)d_in[8];
    const float* Wp    = (const float*)d_in[9];
    const float* bp    = (const float*)d_in[10];
    float* out = (float*)d_out;

    detect_kernel<<<1, 32>>>((const unsigned*)ei, (const unsigned*)batch);
    zero_kernel<<<(NN + 255) / 256, 256>>>();
    convert_kernel<<<(EE + 255) / 256, 256>>>(ei, batch);
    scan1_kernel<<<NCH, 512>>>();
    scan2_kernel<<<1, 256>>>();
    scan3_kernel<<<NCH, 512>>>();
    csrscat_kernel<<<(EE + 255) / 256, 256>>>(eattr);

    float* hbuf = nullptr;
    cudaGetSymbolAddress((void**)&hbuf, d_hbuf);

    pre_kernel<<<(NN * DD / 4 + 255) / 256, 256>>>(x, eps);

    const float* hprev = x;
    for (int l = 0; l < LL; l++) {
        scatter_kernel<<<SC_BLOCKS, 256>>>(hprev, We, be);
        float* hout = hbuf + (size_t)l * NN * DD;
        mlp_kernel<<<(NN + 63) / 64, 256>>>(Wm + l * DD * DD, bm + l * DD,
                                            hout, eps, l);
        hprev = hout;
    }

    pred_kernel<<<(GG * TT + 255) / 256, 256>>>(Wp, bp, out);
}

// round 9
// speedup vs baseline: 1.3587x; 1.0901x over previous
#include <cuda_runtime.h>

#define NN 100000
#define EE 1250000
#define DD 64
#define LL 5
#define GG 128
#define TT 37
#define DE 7
#define NCH 196          // ceil(NN/512)

#define SC_BLOCKS 592                     // 148 SMs x 4 resident blocks
#define SC_HW (SC_BLOCKS * 16)            // half-warps in scatter grid
#define EPH ((EE + SC_HW - 1) / SC_HW)    // edges per half-warp chunk

// ---------------- device scratch ----------------
__device__ float d_hbuf[LL * NN * DD];    // per-layer node embeddings
__device__ float d_agg[NN * DD];
__device__ int2  d_edge[EE];              // raw {src,dst}
__device__ int2  d_edgeP[EE];             // {src,dst} sorted by src
__device__ float d_eattrP[EE * 8];        // edge attrs permuted to src order
__device__ int   d_deg[NN];               // out-degree
__device__ int   d_off[NN];
__device__ int   d_cur[NN];
__device__ int   d_chtot[256];
__device__ int   d_choff[256];
__device__ int   d_batch32[NN];
__device__ float d_gpool[GG * LL * DD];
__device__ int   d_flags[2];

// ---------------- dtype detection ----------------
__global__ void detect_kernel(const unsigned* __restrict__ ei,
                              const unsigned* __restrict__ batch) {
    if (threadIdx.x == 0 && blockIdx.x == 0) {
        int f = 1;
        for (int k = 0; k < 64; k++)
            if (ei[1000001 + 2 * k] != 0u) { f = 0; break; }
        d_flags[0] = f;
        int fb = 1;
        for (int k = 0; k < 64; k++)
            if (batch[(NN - 1) - 2 * k] != 0u) { fb = 0; break; }
        d_flags[1] = fb;
    }
}

// ---------------- zero deg + gpool ----------------
__global__ void zero_kernel() {
    int i = blockIdx.x * blockDim.x + threadIdx.x;
    if (i < NN) d_deg[i] = 0;
    if (i < GG * LL * DD) d_gpool[i] = 0.0f;
}

// ---------------- convert indices (+ out-degree histogram) ----------------
__global__ void convert_kernel(const void* __restrict__ ei,
                               const void* __restrict__ batch) {
    int i = blockIdx.x * blockDim.x + threadIdx.x;
    int e64 = d_flags[0];
    int b64 = d_flags[1];
    if (i < EE) {
        int s, d;
        if (e64) {
            const long long* p = (const long long*)ei;
            s = (int)p[i]; d = (int)p[i + EE];
        } else {
            const int* p = (const int*)ei;
            s = p[i]; d = p[i + EE];
        }
        d_edge[i] = make_int2(s, d);
        atomicAdd(&d_deg[s], 1);
    }
    if (i < NN) {
        if (b64) {
            const long long* p = (const long long*)batch;
            d_batch32[i] = (int)p[i];
        } else {
            const int* p = (const int*)batch;
            d_batch32[i] = p[i];
        }
    }
}

// ---------------- scans ----------------
__global__ void scan1_kernel() {
    __shared__ int sm[512];
    int t = threadIdx.x;
    int g = blockIdx.x * 512 + t;
    int v = (g < NN) ? d_deg[g] : 0;
    sm[t] = v;
    __syncthreads();
    for (int off = 1; off < 512; off <<= 1) {
        int x = (t >= off) ? sm[t - off] : 0;
        __syncthreads();
        sm[t] += x;
        __syncthreads();
    }
    if (g < NN) d_off[g] = sm[t] - v;
    if (t == 511) d_chtot[blockIdx.x] = sm[511];
}

__global__ void scan2_kernel() {
    __shared__ int sm[256];
    int t = threadIdx.x;
    int v = (t < NCH) ? d_chtot[t] : 0;
    sm[t] = v;
    __syncthreads();
    for (int off = 1; off < 256; off <<= 1) {
        int x = (t >= off) ? sm[t - off] : 0;
        __syncthreads();
        sm[t] += x;
        __syncthreads();
    }
    if (t < NCH) d_choff[t] = sm[t] - v;
}

__global__ void scan3_kernel() {
    int t = threadIdx.x;
    int g = blockIdx.x * 512 + t;
    if (g < NN) {
        int o = d_off[g] + d_choff[blockIdx.x];
        d_off[g] = o;
        d_cur[g] = o;
    }
}

// ---------------- permute edges into src-sorted order ---------------------
__global__ void csrscat_kernel(const float* __restrict__ eattr) {
    int e = blockIdx.x * blockDim.x + threadIdx.x;
    if (e >= EE) return;
    int2 sd = d_edge[e];
    int pos = atomicAdd(&d_cur[sd.x], 1);
    d_edgeP[pos] = sd;
    const float* ea = eattr + (size_t)e * DE;
    float4 v0 = make_float4(ea[0], ea[1], ea[2], ea[3]);
    float4 v1 = make_float4(ea[4], ea[5], ea[6], 0.0f);
    float4* p = (float4*)(d_eattrP + (size_t)pos * 8);
    p[0] = v0; p[1] = v1;
}

// ---------------- agg = (1 + eps[0]) * x  (layer 0 only) ------------------
__global__ void pre_kernel(const float* __restrict__ hprev,
                           const float* __restrict__ eps) {
    int i = blockIdx.x * blockDim.x + threadIdx.x;
    const int n4 = NN * DD / 4;
    if (i >= n4) return;
    float s = 1.0f + __ldg(eps);
    float4 v = ((const float4*)hprev)[i];
    v.x *= s; v.y *= s; v.z *= s; v.w *= s;
    ((float4*)d_agg)[i] = v;
}

// ---------------- scatter: agg[dst] += relu(h[src] + edge_emb) ------------
// Edges sorted by src; each half-warp owns a CONTIGUOUS chunk. h[src] is kept
// in registers and reloaded ONLY when src changes (~8% of edges).
__global__ void __launch_bounds__(256, 4) scatter_kernel(
        const float* __restrict__ hprev,
        const float* __restrict__ We,
        const float* __restrict__ be) {
    int lane = threadIdx.x & 31;
    int c = (lane & 15) * 4;

    float4 w0 = *(const float4*)(We + 0 * DD + c);
    float4 w1 = *(const float4*)(We + 1 * DD + c);
    float4 w2 = *(const float4*)(We + 2 * DD + c);
    float4 w3 = *(const float4*)(We + 3 * DD + c);
    float4 w4 = *(const float4*)(We + 4 * DD + c);
    float4 w5 = *(const float4*)(We + 5 * DD + c);
    float4 w6 = *(const float4*)(We + 6 * DD + c);
    float4 bv = *(const float4*)(be + c);

    int hwid = (blockIdx.x * blockDim.x + threadIdx.x) >> 4;
    long long e0 = (long long)hwid * EPH;
    long long e1 = e0 + EPH;
    if (e1 > EE) e1 = EE;

    int sprev = -1;
    float4 hv = make_float4(0.f, 0.f, 0.f, 0.f);

#pragma unroll 2
    for (long long e = e0; e < e1; e++) {
        int2 sd = __ldg(&d_edgeP[e]);
        float4 a0 = __ldg((const float4*)(d_eattrP + (size_t)e * 8));
        float4 a1 = __ldg((const float4*)(d_eattrP + (size_t)e * 8 + 4));
        if (sd.x != sprev) {
            hv = __ldg((const float4*)(hprev + (size_t)sd.x * DD + c));
            sprev = sd.x;
        }

        float m0 = bv.x, m1 = bv.y, m2 = bv.z, m3 = bv.w;
        m0 = fmaf(a0.x, w0.x, m0); m1 = fmaf(a0.x, w0.y, m1);
        m2 = fmaf(a0.x, w0.z, m2); m3 = fmaf(a0.x, w0.w, m3);
        m0 = fmaf(a0.y, w1.x, m0); m1 = fmaf(a0.y, w1.y, m1);
        m2 = fmaf(a0.y, w1.z, m2); m3 = fmaf(a0.y, w1.w, m3);
        m0 = fmaf(a0.z, w2.x, m0); m1 = fmaf(a0.z, w2.y, m1);
        m2 = fmaf(a0.z, w2.z, m2); m3 = fmaf(a0.z, w2.w, m3);
        m0 = fmaf(a0.w, w3.x, m0); m1 = fmaf(a0.w, w3.y, m1);
        m2 = fmaf(a0.w, w3.z, m2); m3 = fmaf(a0.w, w3.w, m3);
        m0 = fmaf(a1.x, w4.x, m0); m1 = fmaf(a1.x, w4.y, m1);
        m2 = fmaf(a1.x, w4.z, m2); m3 = fmaf(a1.x, w4.w, m3);
        m0 = fmaf(a1.y, w5.x, m0); m1 = fmaf(a1.y, w5.y, m1);
        m2 = fmaf(a1.y, w5.z, m2); m3 = fmaf(a1.y, w5.w, m3);
        m0 = fmaf(a1.z, w6.x, m0); m1 = fmaf(a1.z, w6.y, m1);
        m2 = fmaf(a1.z, w6.z, m2); m3 = fmaf(a1.z, w6.w, m3);

        m0 = fmaxf(m0 + hv.x, 0.0f);
        m1 = fmaxf(m1 + hv.y, 0.0f);
        m2 = fmaxf(m2 + hv.z, 0.0f);
        m3 = fmaxf(m3 + hv.w, 0.0f);

        float* ap = d_agg + (size_t)sd.y * DD + c;
        asm volatile("red.global.add.v4.f32 [%0], {%1,%2,%3,%4};"
                     :: "l"(ap), "f"(m0), "f"(m1), "f"(m2), "f"(m3)
                     : "memory");
    }
}

// ---------------- MLP + fused pool ---------------------------------------
// h_out = relu(agg @ W + b); agg_next = s*h_out; gpool[batch] += h_out
__global__ void __launch_bounds__(256) mlp_kernel(
        const float* __restrict__ W,
        const float* __restrict__ b,
        float* __restrict__ hout,
        const float* __restrict__ eps, int l) {
    __shared__ float Ws[DD * DD];
    __shared__ float bs[DD];
    __shared__ float u[64 * DD];

    int t = threadIdx.x;
    for (int i = t; i < DD * DD / 4; i += 256)
        ((float4*)Ws)[i] = ((const float4*)W)[i];
    if (t < DD) bs[t] = b[t];

    int node0 = blockIdx.x * 64;
    for (int i = t; i < 64 * 16; i += 256) {
        int node = node0 + (i >> 4);
        float4 v = (node < NN)
            ? ((const float4*)(d_agg + (size_t)node * DD))[i & 15]
            : make_float4(0.f, 0.f, 0.f, 0.f);
        ((float4*)u)[i] = v;
    }
    __syncthreads();

    float snext = (l < LL - 1) ? (1.0f + __ldg(eps + l + 1)) : 0.0f;

    int c4 = (t & 15) * 4;
    int n4 = (t >> 4) * 4;

    float acc[4][4];
#pragma unroll
    for (int ni = 0; ni < 4; ni++) {
        acc[ni][0] = bs[c4 + 0];
        acc[ni][1] = bs[c4 + 1];
        acc[ni][2] = bs[c4 + 2];
        acc[ni][3] = bs[c4 + 3];
    }

#pragma unroll 8
    for (int k = 0; k < DD; k++) {
        float4 w = *(const float4*)(Ws + k * DD + c4);
#pragma unroll
        for (int ni = 0; ni < 4; ni++) {
            float uv = u[(n4 + ni) * DD + k];
            acc[ni][0] = fmaf(uv, w.x, acc[ni][0]);
            acc[ni][1] = fmaf(uv, w.y, acc[ni][1]);
            acc[ni][2] = fmaf(uv, w.z, acc[ni][2]);
            acc[ni][3] = fmaf(uv, w.w, acc[ni][3]);
        }
    }

#pragma unroll
    for (int ni = 0; ni < 4; ni++) {
        int node = node0 + n4 + ni;
        if (node < NN) {
            float o0 = fmaxf(acc[ni][0], 0.0f);
            float o1 = fmaxf(acc[ni][1], 0.0f);
            float o2 = fmaxf(acc[ni][2], 0.0f);
            float o3 = fmaxf(acc[ni][3], 0.0f);
            *(float4*)(hout + (size_t)node * DD + c4) =
                make_float4(o0, o1, o2, o3);
            if (l < LL - 1) {
                *(float4*)(d_agg + (size_t)node * DD + c4) =
                    make_float4(snext * o0, snext * o1, snext * o2, snext * o3);
            }
            int g = d_batch32[node];
            float* gp = d_gpool + (size_t)g * (LL * DD) + l * DD + c4;
            asm volatile("red.global.add.v4.f32 [%0], {%1,%2,%3,%4};"
                         :: "l"(gp), "f"(o0), "f"(o1), "f"(o2), "f"(o3)
                         : "memory");
        }
    }
}

// ---------------- predictor (divides pooled sum by count) ------------------
__device__ __forceinline__ int lower_bound_i(const int* a, int n, int v) {
    int lo = 0, hi = n;
    while (lo < hi) {
        int m = (lo + hi) >> 1;
        if (a[m] < v) lo = m + 1; else hi = m;
    }
    return lo;
}

__global__ void pred_kernel(const float* __restrict__ Wp,
                            const float* __restrict__ bp,
                            float* __restrict__ out) {
    int i = blockIdx.x * blockDim.x + threadIdx.x;
    if (i >= GG * TT) return;
    int g = i / TT, t = i % TT;
    int start = lower_bound_i(d_batch32, NN, g);
    int end   = lower_bound_i(d_batch32, NN, g + 1);
    int cnt = end - start;
    float inv = 1.0f / (float)(cnt > 0 ? cnt : 1);
    const float* gp = d_gpool + g * (LL * DD);
    float s = 0.0f;
    for (int c = 0; c < LL * DD; c++)
        s = fmaf(gp[c], __ldg(Wp + c * TT + t), s);
    out[i] = fmaf(inv, s, __ldg(bp + t));
}

// ---------------- launch -------------------------------------------------
extern "C" void kernel_launch(void* const* d_in, const int* in_sizes, int n_in,
                              void* d_out, int out_size) {
    const float* x     = (const float*)d_in[0];
    const void*  ei    = d_in[1];
    const float* eattr = (const float*)d_in[2];
    const void*  batch = d_in[3];
    const float* We    = (const float*)d_in[4];
    const float* be    = (const float*)d_in[5];
    const float* eps   = (const float*)d_in[6];
    const float* Wm    = (const float*)d_in[7];
    const float* bm    = (const float*)d_in[8];
    const float* Wp    = (const float*)d_in[9];
    const float* bp    = (const float*)d_in[10];
    float* out = (float*)d_out;

    detect_kernel<<<1, 32>>>((const unsigned*)ei, (const unsigned*)batch);
    zero_kernel<<<(NN + 255) / 256, 256>>>();
    convert_kernel<<<(EE + 255) / 256, 256>>>(ei, batch);
    scan1_kernel<<<NCH, 512>>>();
    scan2_kernel<<<1, 256>>>();
    scan3_kernel<<<NCH, 512>>>();
    csrscat_kernel<<<(EE + 255) / 256, 256>>>(eattr);

    float* hbuf = nullptr;
    cudaGetSymbolAddress((void**)&hbuf, d_hbuf);

    pre_kernel<<<(NN * DD / 4 + 255) / 256, 256>>>(x, eps);

    const float* hprev = x;
    for (int l = 0; l < LL; l++) {
        scatter_kernel<<<SC_BLOCKS, 256>>>(hprev, We, be);
        float* hout = hbuf + (size_t)l * NN * DD;
        mlp_kernel<<<(NN + 63) / 64, 256>>>(Wm + l * DD * DD, bm + l * DD,
                                            hout, eps, l);
        hprev = hout;
    }

    pred_kernel<<<(GG * TT + 255) / 256, 256>>>(Wp, bp, out);
}

// round 10
// speedup vs baseline: 1.4542x; 1.0704x over previous
#include <cuda_runtime.h>

#define NN 100000
#define EE 1250000
#define DD 64
#define LL 5
#define GG 128
#define TT 37
#define DE 7
#define NCH 196          // ceil(NN/512)

#define SC_BLOCKS 592                     // 148 SMs x 4 resident blocks
#define SC_HW (SC_BLOCKS * 16)            // half-warps in scatter grid
#define EPH ((EE + SC_HW - 1) / SC_HW)    // edges per half-warp chunk

// ---------------- device scratch ----------------
__device__ float d_hbuf[LL * NN * DD];    // per-layer node embeddings
__device__ float d_agg[NN * DD];
__device__ int2  d_edgeP[EE];             // {src,dst} sorted by src
__device__ float d_eattrP[EE * 8];        // edge attrs permuted to src order
__device__ int   d_deg[NN];               // out-degree
__device__ int   d_off[NN];
__device__ int   d_cur[NN];
__device__ int   d_chtot[256];
__device__ int   d_choff[256];
__device__ int   d_batch32[NN];
__device__ float d_gpool[GG * LL * DD];
__device__ int   d_flags[2];

// ---------------- zero + dtype detection (merged) -------------------------
__global__ void init_kernel(const unsigned* __restrict__ ei,
                            const unsigned* __restrict__ batch) {
    int i = blockIdx.x * blockDim.x + threadIdx.x;
    if (i < NN) d_deg[i] = 0;
    if (i < GG * LL * DD) d_gpool[i] = 0.0f;
    if (i == 0) {
        int f = 1;
        for (int k = 0; k < 64; k++)
            if (ei[1000001 + 2 * k] != 0u) { f = 0; break; }
        d_flags[0] = f;
        int fb = 1;
        for (int k = 0; k < 64; k++)
            if (batch[(NN - 1) - 2 * k] != 0u) { fb = 0; break; }
        d_flags[1] = fb;
    }
}

// ---------------- histogram + batch convert -------------------------------
__global__ void convert_kernel(const void* __restrict__ ei,
                               const void* __restrict__ batch) {
    int i = blockIdx.x * blockDim.x + threadIdx.x;
    int e64 = d_flags[0];
    int b64 = d_flags[1];
    if (i < EE) {
        int s;
        if (e64) s = (int)((const long long*)ei)[i];
        else     s = ((const int*)ei)[i];
        atomicAdd(&d_deg[s], 1);
    }
    if (i < NN) {
        if (b64) d_batch32[i] = (int)((const long long*)batch)[i];
        else     d_batch32[i] = ((const int*)batch)[i];
    }
}

// ---------------- scans ----------------
__global__ void scan1_kernel() {
    __shared__ int wsum[16];
    int t = threadIdx.x;
    int lane = t & 31, w = t >> 5;
    int g = blockIdx.x * 512 + t;
    int v = (g < NN) ? d_deg[g] : 0;
    // warp inclusive scan
    int s = v;
#pragma unroll
    for (int off = 1; off < 32; off <<= 1) {
        int x = __shfl_up_sync(0xffffffffu, s, off);
        if (lane >= off) s += x;
    }
    if (lane == 31) wsum[w] = s;
    __syncthreads();
    if (w == 0) {
        int ws = (lane < 16) ? wsum[lane] : 0;
#pragma unroll
        for (int off = 1; off < 16; off <<= 1) {
            int x = __shfl_up_sync(0xffffffffu, ws, off);
            if (lane >= off) ws += x;
        }
        if (lane < 16) wsum[lane] = ws;
    }
    __syncthreads();
    int woff = (w > 0) ? wsum[w - 1] : 0;
    if (g < NN) d_off[g] = woff + s - v;    // exclusive
    if (t == 511) d_chtot[blockIdx.x] = wsum[15];
}

__global__ void scan2_kernel() {
    __shared__ int sm[256];
    int t = threadIdx.x;
    int v = (t < NCH) ? d_chtot[t] : 0;
    sm[t] = v;
    __syncthreads();
    for (int off = 1; off < 256; off <<= 1) {
        int x = (t >= off) ? sm[t - off] : 0;
        __syncthreads();
        sm[t] += x;
        __syncthreads();
    }
    if (t < NCH) d_choff[t] = sm[t] - v;
}

__global__ void scan3_kernel() {
    int t = threadIdx.x;
    int g = blockIdx.x * 512 + t;
    if (g < NN) {
        int o = d_off[g] + d_choff[blockIdx.x];
        d_off[g] = o;
        d_cur[g] = o;
    }
}

// ---------------- permute edges into src-sorted order ---------------------
// Reads edge_index directly (no intermediate d_edge array).
__global__ void csrscat_kernel(const void* __restrict__ ei,
                               const float* __restrict__ eattr) {
    int e = blockIdx.x * blockDim.x + threadIdx.x;
    if (e >= EE) return;
    int e64 = d_flags[0];
    int s, d;
    if (e64) {
        const long long* p = (const long long*)ei;
        s = (int)p[e]; d = (int)p[e + EE];
    } else {
        const int* p = (const int*)ei;
        s = p[e]; d = p[e + EE];
    }
    int pos = atomicAdd(&d_cur[s], 1);
    d_edgeP[pos] = make_int2(s, d);
    const float* ea = eattr + (size_t)e * DE;
    float4 v0 = make_float4(ea[0], ea[1], ea[2], ea[3]);
    float4 v1 = make_float4(ea[4], ea[5], ea[6], 0.0f);
    float4* p4 = (float4*)(d_eattrP + (size_t)pos * 8);
    p4[0] = v0; p4[1] = v1;
}

// ---------------- agg = (1 + eps[0]) * x  (layer 0 only) ------------------
__global__ void pre_kernel(const float* __restrict__ hprev,
                           const float* __restrict__ eps) {
    int i = blockIdx.x * blockDim.x + threadIdx.x;
    const int n4 = NN * DD / 4;
    if (i >= n4) return;
    float s = 1.0f + __ldg(eps);
    float4 v = ((const float4*)hprev)[i];
    v.x *= s; v.y *= s; v.z *= s; v.w *= s;
    ((float4*)d_agg)[i] = v;
}

// ---------------- scatter: agg[dst] += relu(h[src] + edge_emb) ------------
// Edges sorted by src; each half-warp owns a CONTIGUOUS chunk. h[src] kept in
// registers, reloaded only on src change (~8% of edges).
__global__ void __launch_bounds__(256, 4) scatter_kernel(
        const float* __restrict__ hprev,
        const float* __restrict__ We,
        const float* __restrict__ be) {
    int lane = threadIdx.x & 31;
    int c = (lane & 15) * 4;

    float4 w0 = *(const float4*)(We + 0 * DD + c);
    float4 w1 = *(const float4*)(We + 1 * DD + c);
    float4 w2 = *(const float4*)(We + 2 * DD + c);
    float4 w3 = *(const float4*)(We + 3 * DD + c);
    float4 w4 = *(const float4*)(We + 4 * DD + c);
    float4 w5 = *(const float4*)(We + 5 * DD + c);
    float4 w6 = *(const float4*)(We + 6 * DD + c);
    float4 bv = *(const float4*)(be + c);

    int hwid = (blockIdx.x * blockDim.x + threadIdx.x) >> 4;
    long long e0 = (long long)hwid * EPH;
    long long e1 = e0 + EPH;
    if (e1 > EE) e1 = EE;

    int sprev = -1;
    float4 hv = make_float4(0.f, 0.f, 0.f, 0.f);

#pragma unroll 2
    for (long long e = e0; e < e1; e++) {
        int2 sd = __ldg(&d_edgeP[e]);
        float4 a0 = __ldg((const float4*)(d_eattrP + (size_t)e * 8));
        float4 a1 = __ldg((const float4*)(d_eattrP + (size_t)e * 8 + 4));
        if (sd.x != sprev) {
            hv = __ldg((const float4*)(hprev + (size_t)sd.x * DD + c));
            sprev = sd.x;
        }

        float m0 = bv.x, m1 = bv.y, m2 = bv.z, m3 = bv.w;
        m0 = fmaf(a0.x, w0.x, m0); m1 = fmaf(a0.x, w0.y, m1);
        m2 = fmaf(a0.x, w0.z, m2); m3 = fmaf(a0.x, w0.w, m3);
        m0 = fmaf(a0.y, w1.x, m0); m1 = fmaf(a0.y, w1.y, m1);
        m2 = fmaf(a0.y, w1.z, m2); m3 = fmaf(a0.y, w1.w, m3);
        m0 = fmaf(a0.z, w2.x, m0); m1 = fmaf(a0.z, w2.y, m1);
        m2 = fmaf(a0.z, w2.z, m2); m3 = fmaf(a0.z, w2.w, m3);
        m0 = fmaf(a0.w, w3.x, m0); m1 = fmaf(a0.w, w3.y, m1);
        m2 = fmaf(a0.w, w3.z, m2); m3 = fmaf(a0.w, w3.w, m3);
        m0 = fmaf(a1.x, w4.x, m0); m1 = fmaf(a1.x, w4.y, m1);
        m2 = fmaf(a1.x, w4.z, m2); m3 = fmaf(a1.x, w4.w, m3);
        m0 = fmaf(a1.y, w5.x, m0); m1 = fmaf(a1.y, w5.y, m1);
        m2 = fmaf(a1.y, w5.z, m2); m3 = fmaf(a1.y, w5.w, m3);
        m0 = fmaf(a1.z, w6.x, m0); m1 = fmaf(a1.z, w6.y, m1);
        m2 = fmaf(a1.z, w6.z, m2); m3 = fmaf(a1.z, w6.w, m3);

        m0 = fmaxf(m0 + hv.x, 0.0f);
        m1 = fmaxf(m1 + hv.y, 0.0f);
        m2 = fmaxf(m2 + hv.z, 0.0f);
        m3 = fmaxf(m3 + hv.w, 0.0f);

        float* ap = d_agg + (size_t)sd.y * DD + c;
        asm volatile("red.global.add.v4.f32 [%0], {%1,%2,%3,%4};"
                     :: "l"(ap), "f"(m0), "f"(m1), "f"(m2), "f"(m3)
                     : "memory");
    }
}

// ---------------- MLP + fused pool ---------------------------------------
// 512 threads, 128 nodes/block. h_out = relu(agg @ W + b);
// agg_next = s*h_out; gpool[batch] += h_out (run-merged REDs).
__global__ void __launch_bounds__(512) mlp_kernel(
        const float* __restrict__ W,
        const float* __restrict__ b,
        float* __restrict__ hout,
        const float* __restrict__ eps, int l) {
    __shared__ float Ws[DD * DD];     // 16 KB
    __shared__ float bs[DD];
    __shared__ float u[128 * DD];     // 32 KB

    int t = threadIdx.x;
    for (int i = t; i < DD * DD / 4; i += 512)
        ((float4*)Ws)[i] = ((const float4*)W)[i];
    if (t < DD) bs[t] = b[t];

    int node0 = blockIdx.x * 128;
    for (int i = t; i < 128 * 16; i += 512) {
        int node = node0 + (i >> 4);
        float4 v = (node < NN)
            ? ((const float4*)(d_agg + (size_t)node * DD))[i & 15]
            : make_float4(0.f, 0.f, 0.f, 0.f);
        ((float4*)u)[i] = v;
    }
    __syncthreads();

    float snext = (l < LL - 1) ? (1.0f + __ldg(eps + l + 1)) : 0.0f;

    int c4 = (t & 15) * 4;
    int n4 = (t >> 4) * 4;           // 0..124

    float acc[4][4];
#pragma unroll
    for (int ni = 0; ni < 4; ni++) {
        acc[ni][0] = bs[c4 + 0];
        acc[ni][1] = bs[c4 + 1];
        acc[ni][2] = bs[c4 + 2];
        acc[ni][3] = bs[c4 + 3];
    }

#pragma unroll 8
    for (int k = 0; k < DD; k++) {
        float4 w = *(const float4*)(Ws + k * DD + c4);
#pragma unroll
        for (int ni = 0; ni < 4; ni++) {
            float uv = u[(n4 + ni) * DD + k];
            acc[ni][0] = fmaf(uv, w.x, acc[ni][0]);
            acc[ni][1] = fmaf(uv, w.y, acc[ni][1]);
            acc[ni][2] = fmaf(uv, w.z, acc[ni][2]);
            acc[ni][3] = fmaf(uv, w.w, acc[ni][3]);
        }
    }

    // epilogue: write h_out (+scaled agg), pool with run-merged REDs
    float p0 = 0.f, p1 = 0.f, p2 = 0.f, p3 = 0.f;
    int gcur = -1;
#pragma unroll
    for (int ni = 0; ni < 4; ni++) {
        int node = node0 + n4 + ni;
        if (node < NN) {
            float o0 = fmaxf(acc[ni][0], 0.0f);
            float o1 = fmaxf(acc[ni][1], 0.0f);
            float o2 = fmaxf(acc[ni][2], 0.0f);
            float o3 = fmaxf(acc[ni][3], 0.0f);
            *(float4*)(hout + (size_t)node * DD + c4) =
                make_float4(o0, o1, o2, o3);
            if (l < LL - 1) {
                *(float4*)(d_agg + (size_t)node * DD + c4) =
                    make_float4(snext * o0, snext * o1, snext * o2, snext * o3);
            }
            int g = d_batch32[node];
            if (g != gcur) {
                if (gcur >= 0) {
                    float* gp = d_gpool + (size_t)gcur * (LL * DD) + l * DD + c4;
                    asm volatile("red.global.add.v4.f32 [%0], {%1,%2,%3,%4};"
                                 :: "l"(gp), "f"(p0), "f"(p1), "f"(p2), "f"(p3)
                                 : "memory");
                }
                gcur = g;
                p0 = p1 = p2 = p3 = 0.f;
            }
            p0 += o0; p1 += o1; p2 += o2; p3 += o3;
        }
    }
    if (gcur >= 0) {
        float* gp = d_gpool + (size_t)gcur * (LL * DD) + l * DD + c4;
        asm volatile("red.global.add.v4.f32 [%0], {%1,%2,%3,%4};"
                     :: "l"(gp), "f"(p0), "f"(p1), "f"(p2), "f"(p3)
                     : "memory");
    }
}

// ---------------- predictor (divides pooled sum by count) ------------------
__device__ __forceinline__ int lower_bound_i(const int* a, int n, int v) {
    int lo = 0, hi = n;
    while (lo < hi) {
        int m = (lo + hi) >> 1;
        if (a[m] < v) lo = m + 1; else hi = m;
    }
    return lo;
}

__global__ void pred_kernel(const float* __restrict__ Wp,
                            const float* __restrict__ bp,
                            float* __restrict__ out) {
    int i = blockIdx.x * blockDim.x + threadIdx.x;
    if (i >= GG * TT) return;
    int g = i / TT, t = i % TT;
    int start = lower_bound_i(d_batch32, NN, g);
    int end   = lower_bound_i(d_batch32, NN, g + 1);
    int cnt = end - start;
    float inv = 1.0f / (float)(cnt > 0 ? cnt : 1);
    const float* gp = d_gpool + g * (LL * DD);
    float s = 0.0f;
    for (int c = 0; c < LL * DD; c++)
        s = fmaf(gp[c], __ldg(Wp + c * TT + t), s);
    out[i] = fmaf(inv, s, __ldg(bp + t));
}

// ---------------- launch -------------------------------------------------
extern "C" void kernel_launch(void* const* d_in, const int* in_sizes, int n_in,
                              void* d_out, int out_size) {
    const float* x     = (const float*)d_in[0];
    const void*  ei    = d_in[1];
    const float* eattr = (const float*)d_in[2];
    const void*  batch = d_in[3];
    const float* We    = (const float*)d_in[4];
    const float* be    = (const float*)d_in[5];
    const float* eps   = (const float*)d_in[6];
    const float* Wm    = (const float*)d_in[7];
    const float* bm    = (const float*)d_in[8];
    const float* Wp    = (const float*)d_in[9];
    const float* bp    = (const float*)d_in[10];
    float* out = (float*)d_out;

    init_kernel<<<(NN + 255) / 256, 256>>>((const unsigned*)ei,
                                           (const unsigned*)batch);
    convert_kernel<<<(EE + 255) / 256, 256>>>(ei, batch);
    scan1_kernel<<<NCH, 512>>>();
    scan2_kernel<<<1, 256>>>();
    scan3_kernel<<<NCH, 512>>>();
    csrscat_kernel<<<(EE + 255) / 256, 256>>>(ei, eattr);

    float* hbuf = nullptr;
    cudaGetSymbolAddress((void**)&hbuf, d_hbuf);

    pre_kernel<<<(NN * DD / 4 + 255) / 256, 256>>>(x, eps);

    const float* hprev = x;
    for (int l = 0; l < LL; l++) {
        scatter_kernel<<<SC_BLOCKS, 256>>>(hprev, We, be);
        float* hout = hbuf + (size_t)l * NN * DD;
        mlp_kernel<<<(NN + 127) / 128, 512>>>(Wm + l * DD * DD, bm + l * DD,
                                              hout, eps, l);
        hprev = hout;
    }

    pred_kernel<<<(GG * TT + 255) / 256, 256>>>(Wp, bp, out);
}